// round 8
// baseline (speedup 1.0000x reference)
#include <cuda_runtime.h>
#include <cuda_bf16.h>
#include <cstdint>
#include <cstddef>

#define BATCH   4
#define CIN     64
#define COUT    128
#define HH      64
#define WW      1024
#define HO      32
#define WO      512
#define NPIX    65536
#define KTOT    1024
#define OUT0    8388608
#define AZI_C   0.006135923151542565f
#define INC_C   0.0073f

// Wc reordered: column k' = pos*64 + c  (from k = c*16 + pos), bf16 hi/lo
__device__ __nv_bfloat16 g_WcH[COUT * KTOT];
__device__ __nv_bfloat16 g_WcL[COUT * KTOT];
__device__ __nv_bfloat16 g_W2TH[CIN * CIN];   // [c][j]
__device__ __nv_bfloat16 g_W2TL[CIN * CIN];
__device__ float g_Ast[CIN * 16];             // [j][pos]

__device__ __forceinline__ uint32_t smem_u32(const void* p) {
    uint32_t a;
    asm("{ .reg .u64 t; cvta.to.shared.u64 t, %1; cvt.u32.u64 %0, t; }" : "=r"(a) : "l"(p));
    return a;
}
#define SWA(o) ((o) ^ (((o) >> 3) & 0x70))
#define SWC(o) ((o) ^ (((o) >> 5) & 0x70))

__device__ __forceinline__ void sts32(uint32_t saddr, uint32_t v) {
    asm volatile("st.shared.u32 [%0], %1;" :: "r"(saddr), "r"(v) : "memory");
}
__device__ __forceinline__ void cp16(uint32_t saddr, const void* gaddr) {
    asm volatile("cp.async.cg.shared.global [%0], [%1], 16;" :: "r"(saddr), "l"(gaddr));
}
#define CP_COMMIT() asm volatile("cp.async.commit_group;" ::: "memory")
#define CP_WAIT1()  asm volatile("cp.async.wait_group 1;" ::: "memory")
#define CP_WAIT0()  asm volatile("cp.async.wait_group 0;" ::: "memory")

__device__ __forceinline__ void ldsm4(uint32_t* r, uint32_t a) {
    asm volatile("ldmatrix.sync.aligned.m8n8.x4.shared.b16 {%0,%1,%2,%3}, [%4];"
        : "=r"(r[0]), "=r"(r[1]), "=r"(r[2]), "=r"(r[3]) : "r"(a));
}
__device__ __forceinline__ void ldsm4t(uint32_t* r, uint32_t a) {
    asm volatile("ldmatrix.sync.aligned.m8n8.x4.trans.shared.b16 {%0,%1,%2,%3}, [%4];"
        : "=r"(r[0]), "=r"(r[1]), "=r"(r[2]), "=r"(r[3]) : "r"(a));
}
__device__ __forceinline__ void mma16816(float* d, const uint32_t* a, const uint32_t* b) {
    asm volatile(
        "mma.sync.aligned.m16n8k16.row.col.f32.bf16.bf16.f32 "
        "{%0,%1,%2,%3}, {%4,%5,%6,%7}, {%8,%9}, {%0,%1,%2,%3};"
        : "+f"(d[0]), "+f"(d[1]), "+f"(d[2]), "+f"(d[3])
        : "r"(a[0]), "r"(a[1]), "r"(a[2]), "r"(a[3]), "r"(b[0]), "r"(b[1]));
}
__device__ __forceinline__ uint32_t pk_bf2(float lo, float hi) {
    uint32_t r;
    asm("cvt.rn.bf16x2.f32 %0, %1, %2;" : "=r"(r) : "f"(hi), "f"(lo));
    return r;
}

// =====================================================================
// Kernel 0: reorder+split Wc, split W2^T, precompute Ast
// =====================================================================
__global__ void k0_prep(const float* __restrict__ Wc, const float* __restrict__ W2,
                        const float* __restrict__ W1) {
    int i = blockIdx.x * 256 + threadIdx.x;
    if (i < COUT * KTOT) {
        int o = i >> 10, k = i & 1023;
        int c = k >> 4, pos = k & 15;
        int kp = pos * 64 + c;
        float v = Wc[i];
        __nv_bfloat16 h = __float2bfloat16(v);
        g_WcH[o * 1024 + kp] = h;
        g_WcL[o * 1024 + kp] = __float2bfloat16(v - __bfloat162float(h));
    }
    if (i < CIN * CIN) {
        int j = i >> 6, c = i & 63;
        float v = W2[i];
        __nv_bfloat16 h = __float2bfloat16(v);
        g_W2TH[c * 64 + j] = h;
        g_W2TL[c * 64 + j] = __float2bfloat16(v - __bfloat162float(h));
    }
    if (i < CIN * 16) {
        int j = i >> 4, pos = i & 15;
        int u = pos >> 2, v = pos & 3;
        float du = (float)(u - 2), dv = (float)(v - 2);
        float ca = cosf(AZI_C * dv), sa = sinf(AZI_C * dv);
        float ci = cosf(INC_C * du), si = sinf(INC_C * du);
        g_Ast[i] = ca * ci * W1[j] + ca * si * W1[64 + j] + sa * W1[128 + j];
    }
}

// =====================================================================
// Fused kernel: h -> w-GEMM -> m (smem) -> out-GEMM (registers)
// grid (16, 32, 4), 256 threads, 1 CTA/SM.
// smem byte map:
//   0      : hs planes (HSH 32K, HSL 32K)  /  m [512][128B SWA] (time-shared)
//   65536  : Wc stream, 2 stages x 32K (H 16K + L 16K each)
//   131072 : xs f32 [64][264]  (67584)
//   198656 : W2TH (8192) ; 206848 : W2TL (8192)
//   215040 : Ast f32 [64][16] (4096)
//   219136 : W10 (256) ; 219392: b1 (256) ; 219648: b2 (256)
//   219904 : rs f32 [4][66] (1056)   -> total 220960
// =====================================================================
#define M_B     0
#define HSH_B   0
#define HSL_B   32768
#define WC_B    65536
#define XS_B    131072
#define W2TH_B  198656
#define W2TL_B  206848
#define AST_B   215040
#define W10_B   219136
#define B1_B    219392
#define B2_B    219648
#define RS_B    219904
#define SM1_BYTES 220960

__global__ void __launch_bounds__(256, 1)
k1_fused(const float* __restrict__ x, const float* __restrict__ r,
         const float* __restrict__ W1, const float* __restrict__ b1,
         const float* __restrict__ b2, const float* __restrict__ bc,
         float* __restrict__ out, float* __restrict__ rcout)
{
    extern __shared__ float sm[];
    float* xs   = sm + XS_B / 4;
    float* Ast  = sm + AST_B / 4;
    float* W10s = sm + W10_B / 4;
    float* b1s  = sm + B1_B / 4;
    float* b2s  = sm + B2_B / 4;
    float* rs   = sm + RS_B / 4;
    char*  smc  = (char*)sm;
    const uint32_t sb = smem_u32(sm);

    const int tid  = threadIdx.x;
    const int lane = tid & 31;
    const int wid  = tid >> 5;
    const int ho   = blockIdx.y;
    const int bz   = blockIdx.z;
    const int wo0  = blockIdx.x * 32;

    if (tid < 64) { W10s[tid] = W1[tid]; b1s[tid] = b1[tid]; b2s[tid] = b2[tid]; }
    for (int i = tid; i < 1024; i += 256) Ast[i] = g_Ast[i];
    for (int i = tid; i < 4 * 66; i += 256) {
        int v = i / 66, cc = i % 66;
        int rowp = 2 * ho + v;
        int row  = (rowp == 0) ? (HH - 1) : ((rowp == HH + 1) ? 0 : rowp - 1);
        int colp = 2 * wo0 + cc;
        float val;
        if (colp == 0 || colp == WW + 1) val = 100.0f;
        else val = r[((size_t)bz * HH + row) * WW + (colp - 1)];
        rs[i] = val;
    }
    for (int i = tid; i < 4096; i += 256) {
        int row = i >> 6, col = i & 63;
        uint32_t off = SWA(row * 128 + col * 2);
        *(__nv_bfloat16*)(smc + W2TH_B + off) = g_W2TH[i];
        *(__nv_bfloat16*)(smc + W2TL_B + off) = g_W2TL[i];
    }
    // x strip, division-free
    {
        int xr[4];
        #pragma unroll
        for (int v = 0; v < 4; v++) {
            int rowp = 2 * ho + v;
            xr[v] = (rowp == 0) ? (HH - 1) : ((rowp == HH + 1) ? 0 : rowp - 1);
        }
        const int gbase = 2 * wo0 - 1;
        #pragma unroll 4
        for (int it = 0; it < 64; it++) {
            int flat = tid + it * 256;
            int cc = flat & 63;
            int rv = flat >> 6;
            int c = rv >> 2, v = rv & 3;
            int g = gbase + cc;
            float val = 0.0f;
            if (g >= 0)
                val = x[(((size_t)(bz * CIN + c)) * HH + xr[v]) * WW + g];
            xs[c * 264 + v * 66 + cc] = val;
        }
        for (int it = 0; it < 2; it++) {
            int flat = tid + it * 256;
            int cc = 64 + (flat & 1);
            int rv = flat >> 1;
            int c = rv >> 2, v = rv & 3;
            int g = gbase + cc;
            float val = 0.0f;
            if (g < WW)
                val = x[(((size_t)(bz * CIN + c)) * HH + xr[v]) * WW + g];
            xs[c * 264 + v * 66 + cc] = val;
        }
    }

    // out accumulators: warp wid owns o rows [wid*16, wid*16+16), all 32 n
    float oacc[4][4];
    #pragma unroll
    for (int nt = 0; nt < 4; nt++)
        #pragma unroll
        for (int q = 0; q < 4; q++) oacc[nt][q] = 0.0f;

    // Wc chunk loader: chunk = 64 k' cols; stage = ch&1
    auto load_wc = [&](int s, int ch) {
        const uint32_t stage = sb + WC_B + (ch & 1) * 32768;
        const int k0 = s * 512 + ch * 64;
        #pragma unroll
        for (int t = 0; t < 8; t++) {
            int ci = tid + (t & 3) * 256;     // 0..1023
            const __nv_bfloat16* W = (t < 4) ? g_WcH : g_WcL;
            int row = ci >> 3, un = ci & 7;
            uint32_t sa = stage + ((t < 4) ? 0 : 16384) + SWA(row * 128 + un * 16);
            cp16(sa, W + (size_t)row * KTOT + k0 + un * 8);
        }
        CP_COMMIT();
    };

    __syncthreads();

    const int wmg = (wid & 1) * 32;     // w-GEMM warp M (c)
    const int wng = (wid >> 1) * 64;    // w-GEMM warp N (combo)

    for (int s = 0; s < 2; s++) {
        // prefetch Wc chunks 0,1 for this s
        load_wc(s, 0);
        load_wc(s, 1);

        // ---- h compute, shfl-paired bf16x2 split -> hs ----
        {
            int pos  = 8 * s + wid;
            int u = pos >> 2, v = pos & 3;
            int px = lane;
            float R   = rs[v * 66 + 2 * px + u];
            float nrc = -rs[2 * 66 + 2 * px + 2];
            const uint32_t plane = (lane & 1) ? (sb + HSL_B) : (sb + HSH_B);
            const int wordb = (tid & ~1) * 2;
            #pragma unroll 8
            for (int j = 0; j < 64; j++) {
                float t = fmaf(R, Ast[j * 16 + pos], fmaf(nrc, W10s[j], b1s[j]));
                t = (t > 0.0f) ? t : 0.2f * t;
                __nv_bfloat16 hb = __float2bfloat16(t);
                float rem = t - __bfloat162float(hb);
                float t_o   = __shfl_xor_sync(0xffffffffu, t, 1);
                float rem_o = __shfl_xor_sync(0xffffffffu, rem, 1);
                uint32_t wH = pk_bf2(t, t_o);
                uint32_t wL = pk_bf2(rem_o, rem);
                uint32_t word = (lane & 1) ? wL : wH;
                sts32(plane + SWC(j * 512 + wordb), word);
            }
        }
        __syncthreads();

        // ---- w-GEMM into registers ----
        float acc[2][8][4];
        #pragma unroll
        for (int mi = 0; mi < 2; mi++)
            #pragma unroll
            for (int nt = 0; nt < 8; nt++)
                #pragma unroll
                for (int q = 0; q < 4; q++) acc[mi][nt][q] = 0.0f;

        #pragma unroll
        for (int ks = 0; ks < 4; ks++) {
            uint32_t aH[2][4], aL[2][4];
            int arow  = wmg + (lane & 15);
            int acolb = ks * 32 + ((lane >> 4) << 4);
            #pragma unroll
            for (int mi = 0; mi < 2; mi++) {
                uint32_t off = SWA((arow + mi * 16) * 128 + acolb);
                ldsm4(aH[mi], sb + W2TH_B + off);
                ldsm4(aL[mi], sb + W2TL_B + off);
            }
            int browb = (ks * 16 + (lane & 15)) * 512;
            #pragma unroll
            for (int g = 0; g < 4; g++) {
                uint32_t off = SWC(browb + wng * 2 + g * 32 + ((lane >> 4) << 4));
                uint32_t bh[4], bl[4];
                ldsm4t(bh, sb + HSH_B + off);
                ldsm4t(bl, sb + HSL_B + off);
                #pragma unroll
                for (int mi = 0; mi < 2; mi++) {
                    mma16816(acc[mi][2*g],   aH[mi], bh);
                    mma16816(acc[mi][2*g+1], aH[mi], bh + 2);
                    mma16816(acc[mi][2*g],   aL[mi], bh);
                    mma16816(acc[mi][2*g+1], aL[mi], bh + 2);
                    mma16816(acc[mi][2*g],   aH[mi], bl);
                    mma16816(acc[mi][2*g+1], aH[mi], bl + 2);
                }
            }
        }
        __syncthreads();   // hs fully consumed; m region reuse OK

        // ---- phase B: m = (acc+b2)*x -> m smem (512 rows x 128B, SWA) ----
        {
            #pragma unroll
            for (int mi = 0; mi < 2; mi++) {
                int r0 = wmg + mi * 16 + (lane >> 2);
                int r2 = r0 + 8;
                float b2a = b2s[r0], b2b = b2s[r2];
                #pragma unroll
                for (int nt = 0; nt < 8; nt++) {
                    int col0 = wng + nt * 8 + (lane & 3) * 2;
                    int posl = col0 >> 5;
                    int px0  = col0 & 31;
                    int pos  = 8 * s + posl;
                    int u = pos >> 2, v = pos & 3;
                    const float* xr0 = xs + r0 * 264 + v * 66 + u;
                    const float* xr2 = xs + r2 * 264 + v * 66 + u;
                    float xa0 = xr0[2 * px0],     xa1 = xr0[2 * px0 + 2];
                    float xb0 = xr2[2 * px0],     xb1 = xr2[2 * px0 + 2];
                    float m0 = (acc[mi][nt][0] + b2a) * xa0;
                    float m1 = (acc[mi][nt][1] + b2a) * xa1;
                    float m2 = (acc[mi][nt][2] + b2b) * xb0;
                    float m3 = (acc[mi][nt][3] + b2b) * xb1;
                    __nv_bfloat16 h0 = __float2bfloat16(m0), h1 = __float2bfloat16(m1);
                    __nv_bfloat16 h2 = __float2bfloat16(m2), h3 = __float2bfloat16(m3);
                    float l0 = m0 - __bfloat162float(h0), l1 = m1 - __bfloat162float(h1);
                    float l2 = m2 - __bfloat162float(h2), l3 = m3 - __bfloat162float(h3);
                    uint32_t rowa = (uint32_t)(posl * 64 + r0) * 128;
                    uint32_t rowb = (uint32_t)(posl * 64 + r2) * 128;
                    sts32(sb + M_B + SWA(rowa + 2 * px0),      pk_bf2(m0, m1));
                    sts32(sb + M_B + SWA(rowa + 64 + 2 * px0), pk_bf2(l0, l1));
                    sts32(sb + M_B + SWA(rowb + 2 * px0),      pk_bf2(m2, m3));
                    sts32(sb + M_B + SWA(rowb + 64 + 2 * px0), pk_bf2(l2, l3));
                    // note: pk_bf2(m0,m1) re-rounds m0,m1 to bf16 == h0,h1 (same rn)
                }
            }
        }
        __syncthreads();

        // ---- out-GEMM over 8 chunks of 64 k' ----
        for (int ch = 0; ch < 8; ch++) {
            if (ch == 7) { CP_WAIT0(); } else { CP_WAIT1(); }
            __syncthreads();
            const uint32_t stH = sb + WC_B + (ch & 1) * 32768;
            const uint32_t stL = stH + 16384;
            #pragma unroll
            for (int ks = 0; ks < 4; ks++) {
                uint32_t aH[4], aL[4];
                int arow  = wid * 16 + (lane & 15);
                int acolb = ks * 32 + ((lane >> 4) << 4);
                uint32_t aoff = SWA(arow * 128 + acolb);
                ldsm4(aH, stH + aoff);
                ldsm4(aL, stL + aoff);
                int brow = ch * 64 + ks * 16 + (lane & 15);
                #pragma unroll
                for (int g = 0; g < 2; g++) {
                    int nb = (g * 16 + ((lane >> 4) << 3)) * 2;
                    uint32_t bh[4], bl[4];
                    ldsm4t(bh, sb + M_B + SWA(brow * 128 + nb));
                    ldsm4t(bl, sb + M_B + SWA(brow * 128 + 64 + nb));
                    mma16816(oacc[2*g],   aH, bh);
                    mma16816(oacc[2*g+1], aH, bh + 2);
                    mma16816(oacc[2*g],   aL, bh);
                    mma16816(oacc[2*g+1], aL, bh + 2);
                    mma16816(oacc[2*g],   aH, bl);
                    mma16816(oacc[2*g+1], aH, bl + 2);
                }
            }
            __syncthreads();
            if (ch + 2 < 8) load_wc(s, ch + 2);
        }
    }

    // ---- epilogue: bias + store out ----
    {
        const size_t base = (size_t)bz * (COUT * 16384) + (size_t)ho * 512 + wo0;
        int r0 = wid * 16 + (lane >> 2);
        float bv0 = bc[r0], bv1 = bc[r0 + 8];
        float* row0 = out + base + (size_t)r0 * 16384;
        float* row1 = out + base + (size_t)(r0 + 8) * 16384;
        #pragma unroll
        for (int nt = 0; nt < 4; nt++) {
            int col = nt * 8 + (lane & 3) * 2;
            float2 v0, v1;
            v0.x = oacc[nt][0] + bv0; v0.y = oacc[nt][1] + bv0;
            v1.x = oacc[nt][2] + bv1; v1.y = oacc[nt][3] + bv1;
            *(float2*)(row0 + col) = v0;
            *(float2*)(row1 + col) = v1;
        }
    }

    if (rcout != nullptr && tid < 32) {
        rcout[(size_t)bz * 16384 + (size_t)ho * 512 + wo0 + tid] =
            rs[2 * 66 + 2 * tid + 2];
    }
}

extern "C" void kernel_launch(void* const* d_in, const int* in_sizes, int n_in,
                              void* d_out, int out_size) {
    const float* x  = (const float*)d_in[0];
    const float* r  = (const float*)d_in[1];
    const float* W1 = (const float*)d_in[2];
    const float* b1 = (const float*)d_in[3];
    const float* W2 = (const float*)d_in[4];
    const float* b2 = (const float*)d_in[5];
    const float* Wc = (const float*)d_in[6];
    const float* bc = (const float*)d_in[7];
    float* out = (float*)d_out;

    cudaFuncSetAttribute(k1_fused, cudaFuncAttributeMaxDynamicSharedMemorySize, SM1_BYTES);

    float* rcout = (out_size > OUT0) ? (out + OUT0) : nullptr;

    k0_prep<<<(COUT * KTOT + 255) / 256, 256>>>(Wc, W2, W1);
    dim3 g1(16, 32, 4);
    k1_fused<<<g1, 256, SM1_BYTES>>>(x, r, W1, b1, b2, bc, out, rcout);
}